// round 14
// baseline (speedup 1.0000x reference)
#include <cuda_runtime.h>
#include <cuda_fp16.h>
#include <cstdint>

#define N_BLOCKS   512
#define BLOCK_IN   128
#define BLOCK_OUT  128
#define LAYER_IN   65536
#define LAYER_OUT  65536
#define BATCH      2048

__device__ __forceinline__ uint32_t smem_u32(const void* p) {
    uint32_t a;
    asm("{ .reg .u64 t; cvta.to.shared.u64 t, %1; cvt.u32.u64 %0, t; }" : "=r"(a) : "l"(p));
    return a;
}

// ---------------------------------------------------------------------------
// Fused kernel: per (n, 8 batch-tiles). Prologue computes exp(c) -> sB (fp16,
// UNNORMALIZED) + per-column inv sums; epilogue applies inv to the output.
// Tile loop is the proven R6 body: 4 warps, warp tile 64x64, 2 CTAs/SM.
// ---------------------------------------------------------------------------
#define LDA 136                        // halfs per padded smem row (128 + 8)
#define A_TILE_HALFS (128 * LDA)       // 17408 halfs = 34816 B
#define SMEM_TOTAL (2 * A_TILE_HALFS * 2 + 512)   // sB + sA + sInv = 70144 B
#define BT_PER_CTA 8

#define LDSM_X4(R0, R1, R2, R3, ADDR)                                          \
    asm volatile("ldmatrix.sync.aligned.m8n8.x4.shared.b16 {%0,%1,%2,%3}, [%4];" \
                 : "=r"(R0), "=r"(R1), "=r"(R2), "=r"(R3) : "r"(ADDR))

#define LDSM_X4_T(R0, R1, R2, R3, ADDR)                                        \
    asm volatile("ldmatrix.sync.aligned.m8n8.x4.trans.shared.b16 {%0,%1,%2,%3}, [%4];" \
                 : "=r"(R0), "=r"(R1), "=r"(R2), "=r"(R3) : "r"(ADDR))

#define MMA16816(D, A, B0, B1)                                                 \
    asm volatile("mma.sync.aligned.m16n8k16.row.col.f32.f16.f16.f32 "          \
                 "{%0,%1,%2,%3}, {%4,%5,%6,%7}, {%8,%9}, {%0,%1,%2,%3};"       \
                 : "+f"((D)[0]), "+f"((D)[1]), "+f"((D)[2]), "+f"((D)[3])      \
                 : "r"((A)[0]), "r"((A)[1]), "r"((A)[2]), "r"((A)[3]),         \
                   "r"(B0), "r"(B1))

__device__ __forceinline__ void load_a_tile(const float* __restrict__ xb, __half* sA, int tid) {
#pragma unroll
    for (int i = 0; i < 32; i++) {
        int idx = tid + i * 128;              // 0..4095
        int r   = idx >> 5;
        int k4  = (idx & 31) << 2;
        float4 v = *(const float4*)(xb + (size_t)r * LAYER_IN + k4);
        __half2 h01 = __floats2half2_rn(v.x, v.y);
        __half2 h23 = __floats2half2_rn(v.z, v.w);
        uint2 pk = make_uint2(*(uint32_t*)&h01, *(uint32_t*)&h23);
        *(uint2*)&sA[r * LDA + k4] = pk;
    }
}

__global__ __launch_bounds__(128, 2)
void gemm_kernel(const float* __restrict__ x, const float* __restrict__ c,
                 float* __restrict__ out) {
    extern __shared__ __half smem[];
    __half* sB = smem;                         // [128 m][LDA] unnormalized exp(c)
    __half* sA = smem + A_TILE_HALFS;
    float* sInv = (float*)(smem + 2 * A_TILE_HALFS);   // [128] per-o 1/sum

    const int tid  = threadIdx.x;
    const int wid  = tid >> 5;
    const int lane = tid & 31;
    const int n    = blockIdx.x;
    const int btg  = blockIdx.y;

    // ---- prologue A: exp(c) -> sB (fp16, unnormalized); colsum in register.
    //      thread tid owns output column o = tid. Row-coalesced LDG.
    {
        const float* cb = c + (size_t)n * (BLOCK_IN * BLOCK_OUT);
        float colsum = 0.f;
#pragma unroll 8
        for (int m = 0; m < 128; m++) {
            float e = __expf(cb[m * 128 + tid]);
            colsum += e;
            sB[m * LDA + tid] = __float2half(e);
        }
        sInv[tid] = 1.f / colsum;
    }

    // ---- prologue B: first x tile -> sA ----
    const float* xcol = x + (size_t)n * 128;
    load_a_tile(xcol + (size_t)(btg * BT_PER_CTA * 128) * LAYER_IN, sA, tid);
    __syncthreads();

    const int warp_m = wid & 1;
    const int warp_n = wid >> 1;
    const int lr = lane & 15;
    const int lc = (lane >> 4) << 3;

    for (int t = 0; t < BT_PER_CTA; t++) {
        const int bt = btg * BT_PER_CTA + t;

        float acc[4][8][4];
#pragma unroll
        for (int mt = 0; mt < 4; mt++)
#pragma unroll
            for (int nt = 0; nt < 8; nt++)
#pragma unroll
                for (int j = 0; j < 4; j++) acc[mt][nt][j] = 0.f;

#pragma unroll
        for (int ks = 0; ks < 8; ks++) {
            const int k = ks * 16;

            uint32_t a[4][4];
#pragma unroll
            for (int mt = 0; mt < 4; mt++) {
                int row = warp_m * 64 + mt * 16 + lr;
                uint32_t addr = smem_u32(&sA[row * LDA + k + lc]);
                LDSM_X4(a[mt][0], a[mt][1], a[mt][2], a[mt][3], addr);
            }

            uint32_t b[8][2];
#pragma unroll
            for (int qq = 0; qq < 4; qq++) {
                int nn = warp_n * 64 + qq * 16;
                uint32_t addr = smem_u32(&sB[(k + lr) * LDA + nn + lc]);
                LDSM_X4_T(b[qq * 2][0], b[qq * 2][1], b[qq * 2 + 1][0], b[qq * 2 + 1][1], addr);
            }

#pragma unroll
            for (int mt = 0; mt < 4; mt++)
#pragma unroll
                for (int nt = 0; nt < 8; nt++)
                    MMA16816(acc[mt][nt], a[mt], b[nt][0], b[nt][1]);
        }

        __syncthreads();   // all warps done reading sA before overwrite

        // prefetch next A tile: batched LDG burst, drains under the STGs
        if (t + 1 < BT_PER_CTA) {
            load_a_tile(xcol + (size_t)((bt + 1) * 128) * LAYER_IN, sA, tid);
        }

        // ---- epilogue: scale by sInv (softmax denominator), coalesced stores ----
        float* obase = out + (size_t)(bt * 128) * LAYER_OUT + (size_t)n * 128;
        const int er = lane >> 2;
        const int ec = (lane & 3) << 1;
#pragma unroll
        for (int mt = 0; mt < 4; mt++) {
#pragma unroll
            for (int nt = 0; nt < 8; nt++) {
                int r0 = warp_m * 64 + mt * 16 + er;
                int c0 = warp_n * 64 + nt * 8 + ec;
                float2 iv = *(const float2*)&sInv[c0];
                *(float2*)(obase + (size_t)r0 * LAYER_OUT + c0) =
                    make_float2(acc[mt][nt][0] * iv.x, acc[mt][nt][1] * iv.y);
                *(float2*)(obase + (size_t)(r0 + 8) * LAYER_OUT + c0) =
                    make_float2(acc[mt][nt][2] * iv.x, acc[mt][nt][3] * iv.y);
            }
        }

        __syncthreads();   // sA stores visible before next compute
    }
}

// ---------------------------------------------------------------------------
extern "C" void kernel_launch(void* const* d_in, const int* in_sizes, int n_in,
                              void* d_out, int out_size) {
    (void)in_sizes; (void)n_in; (void)out_size;
    const float* x = (const float*)d_in[0];
    const float* c = (const float*)d_in[1];
    float* out = (float*)d_out;

    cudaFuncSetAttribute(gemm_kernel, cudaFuncAttributeMaxDynamicSharedMemorySize, SMEM_TOTAL);
    gemm_kernel<<<dim3(N_BLOCKS, BATCH / 128 / BT_PER_CTA), 128, SMEM_TOTAL>>>(x, c, out);
}

// round 15
// speedup vs baseline: 1.0926x; 1.0926x over previous
#include <cuda_runtime.h>
#include <cuda_fp16.h>
#include <cstdint>

#define N_BLOCKS   512
#define BLOCK_IN   128
#define BLOCK_OUT  128
#define LAYER_IN   65536
#define LAYER_OUT  65536
#define BATCH      2048

__device__ __forceinline__ uint32_t smem_u32(const void* p) {
    uint32_t a;
    asm("{ .reg .u64 t; cvta.to.shared.u64 t, %1; cvt.u32.u64 %0, t; }" : "=r"(a) : "l"(p));
    return a;
}

// ---------------------------------------------------------------------------
// Fused kernel: per (n, 8 batch-tiles). Prologue computes exp(c) -> sB (fp16,
// UNNORMALIZED, MLP-32 vectorized) + per-column inverse sums via a 2KB smem
// reduction; epilogue applies inv to the output. Tile loop = proven R6 body
// (4 warps, warp tile 64x64, 2 CTAs/SM).
// ---------------------------------------------------------------------------
#define LDA 136                        // halfs per padded smem row (128 + 8)
#define A_TILE_HALFS (128 * LDA)       // 17408 halfs = 34816 B
#define SINV_OFF (2 * A_TILE_HALFS)            // float index base after sB+sA
#define PSUM_OFF (2 * A_TILE_HALFS + 256)      // halfs offset: sInv = 512B = 256 halfs
#define SMEM_TOTAL (2 * A_TILE_HALFS * 2 + 512 + 2048)   // sB+sA+sInv+psum = 72192 B
#define BT_PER_CTA 8

#define LDSM_X4(R0, R1, R2, R3, ADDR)                                          \
    asm volatile("ldmatrix.sync.aligned.m8n8.x4.shared.b16 {%0,%1,%2,%3}, [%4];" \
                 : "=r"(R0), "=r"(R1), "=r"(R2), "=r"(R3) : "r"(ADDR))

#define LDSM_X4_T(R0, R1, R2, R3, ADDR)                                        \
    asm volatile("ldmatrix.sync.aligned.m8n8.x4.trans.shared.b16 {%0,%1,%2,%3}, [%4];" \
                 : "=r"(R0), "=r"(R1), "=r"(R2), "=r"(R3) : "r"(ADDR))

#define MMA16816(D, A, B0, B1)                                                 \
    asm volatile("mma.sync.aligned.m16n8k16.row.col.f32.f16.f16.f32 "          \
                 "{%0,%1,%2,%3}, {%4,%5,%6,%7}, {%8,%9}, {%0,%1,%2,%3};"       \
                 : "+f"((D)[0]), "+f"((D)[1]), "+f"((D)[2]), "+f"((D)[3])      \
                 : "r"((A)[0]), "r"((A)[1]), "r"((A)[2]), "r"((A)[3]),         \
                   "r"(B0), "r"(B1))

__device__ __forceinline__ void load_a_tile(const float* __restrict__ xb, __half* sA, int tid) {
#pragma unroll
    for (int i = 0; i < 32; i++) {
        int idx = tid + i * 128;              // 0..4095
        int r   = idx >> 5;
        int k4  = (idx & 31) << 2;
        float4 v = *(const float4*)(xb + (size_t)r * LAYER_IN + k4);
        __half2 h01 = __floats2half2_rn(v.x, v.y);
        __half2 h23 = __floats2half2_rn(v.z, v.w);
        uint2 pk = make_uint2(*(uint32_t*)&h01, *(uint32_t*)&h23);
        *(uint2*)&sA[r * LDA + k4] = pk;
    }
}

__global__ __launch_bounds__(128, 2)
void gemm_kernel(const float* __restrict__ x, const float* __restrict__ c,
                 float* __restrict__ out) {
    extern __shared__ __half smem[];
    __half* sB  = smem;                         // [128 m][LDA] unnormalized exp(c)
    __half* sA  = smem + A_TILE_HALFS;
    float* sInv = (float*)(smem + SINV_OFF);    // [128] per-o 1/sum
    float* psum = (float*)(smem + PSUM_OFF);    // [4][128] partial column sums

    const int tid  = threadIdx.x;
    const int wid  = tid >> 5;
    const int lane = tid & 31;
    const int n    = blockIdx.x;
    const int btg  = blockIdx.y;

    // ---- prologue A: exp(c) -> sB, MLP-32. thread owns cols cg..cg+3,
    //      rows rs, rs+4, ..., rs+124 (32 independent float4 LDGs). ----
    {
        const float* cb = c + (size_t)n * (BLOCK_IN * BLOCK_OUT);
        const int cg = (tid & 31) << 2;
        const int rs = tid >> 5;                // 0..3
        float s0 = 0.f, s1 = 0.f, s2 = 0.f, s3 = 0.f;
#pragma unroll
        for (int j = 0; j < 32; j++) {
            int m = rs + j * 4;
            float4 v = *(const float4*)(cb + m * 128 + cg);
            float e0 = __expf(v.x), e1 = __expf(v.y), e2 = __expf(v.z), e3 = __expf(v.w);
            s0 += e0; s1 += e1; s2 += e2; s3 += e3;
            __half2 h01 = __floats2half2_rn(e0, e1);
            __half2 h23 = __floats2half2_rn(e2, e3);
            *(uint2*)&sB[m * LDA + cg] = make_uint2(*(uint32_t*)&h01, *(uint32_t*)&h23);
        }
        *(float4*)&psum[rs * 128 + cg] = make_float4(s0, s1, s2, s3);
    }

    // ---- prologue B: first x tile -> sA (LDG burst overlaps exp drain) ----
    const float* xcol = x + (size_t)n * 128;
    load_a_tile(xcol + (size_t)(btg * BT_PER_CTA * 128) * LAYER_IN, sA, tid);
    __syncthreads();

    // fold partial sums: thread tid owns output column o = tid
    sInv[tid] = 1.f / (psum[tid] + psum[128 + tid] + psum[256 + tid] + psum[384 + tid]);
    // (visible to all threads at the post-k-loop __syncthreads before first epilogue)

    const int warp_m = wid & 1;
    const int warp_n = wid >> 1;
    const int lr = lane & 15;
    const int lc = (lane >> 4) << 3;

    for (int t = 0; t < BT_PER_CTA; t++) {
        const int bt = btg * BT_PER_CTA + t;

        float acc[4][8][4];
#pragma unroll
        for (int mt = 0; mt < 4; mt++)
#pragma unroll
            for (int nt = 0; nt < 8; nt++)
#pragma unroll
                for (int j = 0; j < 4; j++) acc[mt][nt][j] = 0.f;

#pragma unroll
        for (int ks = 0; ks < 8; ks++) {
            const int k = ks * 16;

            uint32_t a[4][4];
#pragma unroll
            for (int mt = 0; mt < 4; mt++) {
                int row = warp_m * 64 + mt * 16 + lr;
                uint32_t addr = smem_u32(&sA[row * LDA + k + lc]);
                LDSM_X4(a[mt][0], a[mt][1], a[mt][2], a[mt][3], addr);
            }

            uint32_t b[8][2];
#pragma unroll
            for (int qq = 0; qq < 4; qq++) {
                int nn = warp_n * 64 + qq * 16;
                uint32_t addr = smem_u32(&sB[(k + lr) * LDA + nn + lc]);
                LDSM_X4_T(b[qq * 2][0], b[qq * 2][1], b[qq * 2 + 1][0], b[qq * 2 + 1][1], addr);
            }

#pragma unroll
            for (int mt = 0; mt < 4; mt++)
#pragma unroll
                for (int nt = 0; nt < 8; nt++)
                    MMA16816(acc[mt][nt], a[mt], b[nt][0], b[nt][1]);
        }

        __syncthreads();   // sA readers done; also orders sInv for epilogue

        // prefetch next A tile: batched LDG burst, drains under the STGs
        if (t + 1 < BT_PER_CTA) {
            load_a_tile(xcol + (size_t)((bt + 1) * 128) * LAYER_IN, sA, tid);
        }

        // ---- epilogue: scale by sInv (softmax denominator), coalesced stores ----
        float* obase = out + (size_t)(bt * 128) * LAYER_OUT + (size_t)n * 128;
        const int er = lane >> 2;
        const int ec = (lane & 3) << 1;
#pragma unroll
        for (int mt = 0; mt < 4; mt++) {
#pragma unroll
            for (int nt = 0; nt < 8; nt++) {
                int r0 = warp_m * 64 + mt * 16 + er;
                int c0 = warp_n * 64 + nt * 8 + ec;
                float2 iv = *(const float2*)&sInv[c0];
                *(float2*)(obase + (size_t)r0 * LAYER_OUT + c0) =
                    make_float2(acc[mt][nt][0] * iv.x, acc[mt][nt][1] * iv.y);
                *(float2*)(obase + (size_t)(r0 + 8) * LAYER_OUT + c0) =
                    make_float2(acc[mt][nt][2] * iv.x, acc[mt][nt][3] * iv.y);
            }
        }

        __syncthreads();   // sA stores visible before next compute
    }
}

// ---------------------------------------------------------------------------
extern "C" void kernel_launch(void* const* d_in, const int* in_sizes, int n_in,
                              void* d_out, int out_size) {
    (void)in_sizes; (void)n_in; (void)out_size;
    const float* x = (const float*)d_in[0];
    const float* c = (const float*)d_in[1];
    float* out = (float*)d_out;

    cudaFuncSetAttribute(gemm_kernel, cudaFuncAttributeMaxDynamicSharedMemorySize, SMEM_TOTAL);
    gemm_kernel<<<dim3(N_BLOCKS, BATCH / 128 / BT_PER_CTA), 128, SMEM_TOTAL>>>(x, c, out);
}

// round 16
// speedup vs baseline: 1.3238x; 1.2116x over previous
#include <cuda_runtime.h>
#include <cuda_fp16.h>
#include <cstdint>

#define N_BLOCKS   512
#define BLOCK_IN   128
#define BLOCK_OUT  128
#define LAYER_IN   65536
#define LAYER_OUT  65536
#define BATCH      2048

// softmax(c) as fp16, row-major [n][m][o]  (m = K dim, o = N dim)
__device__ __align__(16) __half g_w[(size_t)N_BLOCKS * BLOCK_IN * BLOCK_OUT];

__device__ __forceinline__ uint32_t smem_u32(const void* p) {
    uint32_t a;
    asm("{ .reg .u64 t; cvta.to.shared.u64 t, %1; cvt.u32.u64 %0, t; }" : "=r"(a) : "l"(p));
    return a;
}

// ---------------------------------------------------------------------------
// Pass 1: softmax over m for each (n, o); write fp16 w[m][o].
// ---------------------------------------------------------------------------
__global__ __launch_bounds__(512) void softmax_kernel(const float* __restrict__ c) {
    extern __shared__ float sm[];
    float* se   = sm;
    float* psum = sm + 16384;

    const int n  = blockIdx.x;
    const int tid = threadIdx.x;
    const int o4 = (tid & 31) * 4;
    const int q  = tid >> 5;
    const float* cn = c + (size_t)n * (BLOCK_IN * BLOCK_OUT);

    float4 s = make_float4(0.f, 0.f, 0.f, 0.f);
#pragma unroll
    for (int j = 0; j < 8; j++) {
        int m = q * 8 + j;
        float4 v = *(const float4*)(cn + m * 128 + o4);
        float4 e = make_float4(__expf(v.x), __expf(v.y), __expf(v.z), __expf(v.w));
        *(float4*)(se + m * 128 + o4) = e;
        s.x += e.x; s.y += e.y; s.z += e.z; s.w += e.w;
    }
    *(float4*)(psum + q * 128 + o4) = s;
    __syncthreads();

    float4 tot = make_float4(0.f, 0.f, 0.f, 0.f);
#pragma unroll
    for (int k = 0; k < 16; k++) {
        float4 p = *(const float4*)(psum + k * 128 + o4);
        tot.x += p.x; tot.y += p.y; tot.z += p.z; tot.w += p.w;
    }
    float4 inv = make_float4(1.f / tot.x, 1.f / tot.y, 1.f / tot.z, 1.f / tot.w);

    __half* w = g_w + (size_t)n * (BLOCK_IN * BLOCK_OUT);
#pragma unroll
    for (int j = 0; j < 8; j++) {
        int m = q * 8 + j;
        float4 e = *(const float4*)(se + m * 128 + o4);
        __half2 h01 = __floats2half2_rn(e.x * inv.x, e.y * inv.y);
        __half2 h23 = __floats2half2_rn(e.z * inv.z, e.w * inv.w);
        uint2 pk = make_uint2(*(uint32_t*)&h01, *(uint32_t*)&h23);
        *(uint2*)(w + m * 128 + o4) = pk;
    }
}

// ---------------------------------------------------------------------------
// Pass 2: R6 geometry (128 thr, 4 warps, warp tile 64x64, 2 CTAs/SM, grid
// 2048 = 6.9 full waves) with the R12 half-tile cp.async pipeline.
// ---------------------------------------------------------------------------
#define LDA 136
#define SB_BYTES   (128 * LDA * 2)
#define SA_BYTES   (128 * LDA * 2)
#define STAGE_BYTES 32768
#define SMEM_TOTAL (SB_BYTES + SA_BYTES + STAGE_BYTES)   // 102400
#define BT_PER_CTA 4

#define LDSM_X4(R0, R1, R2, R3, ADDR)                                          \
    asm volatile("ldmatrix.sync.aligned.m8n8.x4.shared.b16 {%0,%1,%2,%3}, [%4];" \
                 : "=r"(R0), "=r"(R1), "=r"(R2), "=r"(R3) : "r"(ADDR))

#define LDSM_X4_T(R0, R1, R2, R3, ADDR)                                        \
    asm volatile("ldmatrix.sync.aligned.m8n8.x4.trans.shared.b16 {%0,%1,%2,%3}, [%4];" \
                 : "=r"(R0), "=r"(R1), "=r"(R2), "=r"(R3) : "r"(ADDR))

#define MMA16816(D, A, B0, B1)                                                 \
    asm volatile("mma.sync.aligned.m16n8k16.row.col.f32.f16.f16.f32 "          \
                 "{%0,%1,%2,%3}, {%4,%5,%6,%7}, {%8,%9}, {%0,%1,%2,%3};"       \
                 : "+f"((D)[0]), "+f"((D)[1]), "+f"((D)[2]), "+f"((D)[3])      \
                 : "r"((A)[0]), "r"((A)[1]), "r"((A)[2]), "r"((A)[3]),         \
                   "r"(B0), "r"(B1))

__device__ __forceinline__ void cp16(uint32_t dst_smem, const void* src) {
    asm volatile("cp.async.cg.shared.global [%0], [%1], 16;" :: "r"(dst_smem), "l"(src));
}
#define CP_COMMIT() asm volatile("cp.async.commit_group;" ::: "memory")
#define CP_WAIT0()  asm volatile("cp.async.wait_group 0;" ::: "memory")

__device__ __forceinline__ void stage_half(const float* __restrict__ xb, int khalf,
                                           uint32_t stage_s, int tid) {
#pragma unroll
    for (int i = 0; i < 16; i++) {
        int idx = tid + i * 128;               // 0..2047
        int r   = idx >> 4;
        int k4  = (idx & 15) << 2;
        cp16(stage_s + idx * 16, xb + (size_t)r * LAYER_IN + khalf * 64 + k4);
    }
}

__device__ __forceinline__ void convert_half(const float* stage, __half* sA, int khalf, int tid) {
#pragma unroll
    for (int i = 0; i < 16; i++) {
        int idx = tid + i * 128;
        float4 v = *(const float4*)(stage + idx * 4);
        int r  = idx >> 4;
        int k4 = (idx & 15) << 2;
        __half2 h01 = __floats2half2_rn(v.x, v.y);
        __half2 h23 = __floats2half2_rn(v.z, v.w);
        uint2 pk = make_uint2(*(uint32_t*)&h01, *(uint32_t*)&h23);
        *(uint2*)&sA[r * LDA + khalf * 64 + k4] = pk;
    }
}

__global__ __launch_bounds__(128, 2)
void gemm_kernel(const float* __restrict__ x, float* __restrict__ out) {
    extern __shared__ char smem[];
    __half* sB   = (__half*)smem;
    __half* sA   = (__half*)(smem + SB_BYTES);
    float* stage = (float*)(smem + SB_BYTES + SA_BYTES);
    const uint32_t stage_s = smem_u32(stage);

    const int tid  = threadIdx.x;
    const int wid  = tid >> 5;
    const int lane = tid & 31;
    const int n    = blockIdx.x;
    const int btg  = blockIdx.y;

    const float* xcol = x + (size_t)n * 128;

    // ---- prologue: w -> sB, first x tile -> sA ----
    {
        const uint4* wsrc = (const uint4*)(g_w + (size_t)n * (BLOCK_IN * BLOCK_OUT));
#pragma unroll
        for (int i = 0; i < 16; i++) {
            int idx = tid + i * 128;
            int r   = idx >> 4;
            int c   = (idx & 15) << 3;
            *(uint4*)&sB[r * LDA + c] = wsrc[idx];
        }
    }
    {
        const float* xb = xcol + (size_t)(btg * BT_PER_CTA * 128) * LAYER_IN;
#pragma unroll
        for (int i = 0; i < 32; i++) {
            int idx = tid + i * 128;
            int r   = idx >> 5;
            int k4  = (idx & 31) << 2;
            float4 v = *(const float4*)(xb + (size_t)r * LAYER_IN + k4);
            __half2 h01 = __floats2half2_rn(v.x, v.y);
            __half2 h23 = __floats2half2_rn(v.z, v.w);
            uint2 pk = make_uint2(*(uint32_t*)&h01, *(uint32_t*)&h23);
            *(uint2*)&sA[r * LDA + k4] = pk;
        }
    }
    __syncthreads();

    const int warp_m = wid & 1;
    const int warp_n = wid >> 1;
    const int lr = lane & 15;
    const int lc = (lane >> 4) << 3;

    for (int t = 0; t < BT_PER_CTA; t++) {
        const int bt = btg * BT_PER_CTA + t;
        const bool pf = (t + 1 < BT_PER_CTA);
        const float* xnext = xcol + (size_t)((bt + 1) * 128) * LAYER_IN;

        if (pf) { stage_half(xnext, 0, stage_s, tid); CP_COMMIT(); }

        float acc[4][8][4];
#pragma unroll
        for (int mt = 0; mt < 4; mt++)
#pragma unroll
            for (int nt = 0; nt < 8; nt++)
#pragma unroll
                for (int j = 0; j < 4; j++) acc[mt][nt][j] = 0.f;

        // ---- ks 0..3: reads sA cols 0-63 ----
#pragma unroll
        for (int ks = 0; ks < 4; ks++) {
            const int k = ks * 16;
            uint32_t a[4][4];
#pragma unroll
            for (int mt = 0; mt < 4; mt++) {
                int row = warp_m * 64 + mt * 16 + lr;
                uint32_t addr = smem_u32(&sA[row * LDA + k + lc]);
                LDSM_X4(a[mt][0], a[mt][1], a[mt][2], a[mt][3], addr);
            }
            uint32_t b[8][2];
#pragma unroll
            for (int qq = 0; qq < 4; qq++) {
                int nn = warp_n * 64 + qq * 16;
                uint32_t addr = smem_u32(&sB[(k + lr) * LDA + nn + lc]);
                LDSM_X4_T(b[qq * 2][0], b[qq * 2][1], b[qq * 2 + 1][0], b[qq * 2 + 1][1], addr);
            }
#pragma unroll
            for (int mt = 0; mt < 4; mt++)
#pragma unroll
                for (int nt = 0; nt < 8; nt++)
                    MMA16816(acc[mt][nt], a[mt], b[nt][0], b[nt][1]);
        }

        // ---- mid: fold half0 into sA cols 0-63, launch half1 ----
        if (pf) {
            CP_WAIT0();
            __syncthreads();
            convert_half(stage, sA, 0, tid);
            stage_half(xnext, 1, stage_s, tid);
            CP_COMMIT();
        }

        // ---- ks 4..7: reads sA cols 64-127 ----
#pragma unroll
        for (int ks = 4; ks < 8; ks++) {
            const int k = ks * 16;
            uint32_t a[4][4];
#pragma unroll
            for (int mt = 0; mt < 4; mt++) {
                int row = warp_m * 64 + mt * 16 + lr;
                uint32_t addr = smem_u32(&sA[row * LDA + k + lc]);
                LDSM_X4(a[mt][0], a[mt][1], a[mt][2], a[mt][3], addr);
            }
            uint32_t b[8][2];
#pragma unroll
            for (int qq = 0; qq < 4; qq++) {
                int nn = warp_n * 64 + qq * 16;
                uint32_t addr = smem_u32(&sB[(k + lr) * LDA + nn + lc]);
                LDSM_X4_T(b[qq * 2][0], b[qq * 2][1], b[qq * 2 + 1][0], b[qq * 2 + 1][1], addr);
            }
#pragma unroll
            for (int mt = 0; mt < 4; mt++)
#pragma unroll
                for (int nt = 0; nt < 8; nt++)
                    MMA16816(acc[mt][nt], a[mt], b[nt][0], b[nt][1]);
        }

        // ---- epilogue (stores drain under the tail wait/convert) ----
        float* obase = out + (size_t)(bt * 128) * LAYER_OUT + (size_t)n * 128;
        const int er = lane >> 2;
        const int ec = (lane & 3) << 1;
#pragma unroll
        for (int mt = 0; mt < 4; mt++) {
#pragma unroll
            for (int nt = 0; nt < 8; nt++) {
                int r0 = warp_m * 64 + mt * 16 + er;
                int c0 = warp_n * 64 + nt * 8 + ec;
                *(float2*)(obase + (size_t)r0 * LAYER_OUT + c0) =
                    make_float2(acc[mt][nt][0], acc[mt][nt][1]);
                *(float2*)(obase + (size_t)(r0 + 8) * LAYER_OUT + c0) =
                    make_float2(acc[mt][nt][2], acc[mt][nt][3]);
            }
        }

        // ---- tail: fold half1 into sA cols 64-127 ----
        if (pf) {
            CP_WAIT0();
            __syncthreads();
            convert_half(stage, sA, 1, tid);
            __syncthreads();
        }
    }
}

// ---------------------------------------------------------------------------
extern "C" void kernel_launch(void* const* d_in, const int* in_sizes, int n_in,
                              void* d_out, int out_size) {
    (void)in_sizes; (void)n_in; (void)out_size;
    const float* x = (const float*)d_in[0];
    const float* c = (const float*)d_in[1];
    float* out = (float*)d_out;

    cudaFuncSetAttribute(softmax_kernel, cudaFuncAttributeMaxDynamicSharedMemorySize, 73728);
    cudaFuncSetAttribute(gemm_kernel,    cudaFuncAttributeMaxDynamicSharedMemorySize, SMEM_TOTAL);

    softmax_kernel<<<N_BLOCKS, 512, 73728>>>(c);
    gemm_kernel<<<dim3(N_BLOCKS, BATCH / 128 / BT_PER_CTA), 128, SMEM_TOTAL>>>(x, out);
}

// round 17
// speedup vs baseline: 1.4880x; 1.1240x over previous
#include <cuda_runtime.h>
#include <cuda_fp16.h>
#include <cstdint>

#define N_BLOCKS   512
#define BLOCK_IN   128
#define BLOCK_OUT  128
#define LAYER_IN   65536
#define LAYER_OUT  65536
#define BATCH      2048

// softmax(c) as fp16, row-major [n][m][o]  (m = K dim, o = N dim)
__device__ __align__(16) __half g_w[(size_t)N_BLOCKS * BLOCK_IN * BLOCK_OUT];

__device__ __forceinline__ uint32_t smem_u32(const void* p) {
    uint32_t a;
    asm("{ .reg .u64 t; cvta.to.shared.u64 t, %1; cvt.u32.u64 %0, t; }" : "=r"(a) : "l"(p));
    return a;
}

// ---------------------------------------------------------------------------
// Pass 1: softmax over m for each (n, o); write fp16 w[m][o].
// ---------------------------------------------------------------------------
__global__ __launch_bounds__(512) void softmax_kernel(const float* __restrict__ c) {
    extern __shared__ float sm[];
    float* se   = sm;
    float* psum = sm + 16384;

    const int n  = blockIdx.x;
    const int tid = threadIdx.x;
    const int o4 = (tid & 31) * 4;
    const int q  = tid >> 5;
    const float* cn = c + (size_t)n * (BLOCK_IN * BLOCK_OUT);

    float4 s = make_float4(0.f, 0.f, 0.f, 0.f);
#pragma unroll
    for (int j = 0; j < 8; j++) {
        int m = q * 8 + j;
        float4 v = *(const float4*)(cn + m * 128 + o4);
        float4 e = make_float4(__expf(v.x), __expf(v.y), __expf(v.z), __expf(v.w));
        *(float4*)(se + m * 128 + o4) = e;
        s.x += e.x; s.y += e.y; s.z += e.z; s.w += e.w;
    }
    *(float4*)(psum + q * 128 + o4) = s;
    __syncthreads();

    float4 tot = make_float4(0.f, 0.f, 0.f, 0.f);
#pragma unroll
    for (int k = 0; k < 16; k++) {
        float4 p = *(const float4*)(psum + k * 128 + o4);
        tot.x += p.x; tot.y += p.y; tot.z += p.z; tot.w += p.w;
    }
    float4 inv = make_float4(1.f / tot.x, 1.f / tot.y, 1.f / tot.z, 1.f / tot.w);

    __half* w = g_w + (size_t)n * (BLOCK_IN * BLOCK_OUT);
#pragma unroll
    for (int j = 0; j < 8; j++) {
        int m = q * 8 + j;
        float4 e = *(const float4*)(se + m * 128 + o4);
        __half2 h01 = __floats2half2_rn(e.x * inv.x, e.y * inv.y);
        __half2 h23 = __floats2half2_rn(e.z * inv.z, e.w * inv.w);
        uint2 pk = make_uint2(*(uint32_t*)&h01, *(uint32_t*)&h23);
        *(uint2*)(w + m * 128 + o4) = pk;
    }
}

// ---------------------------------------------------------------------------
// Pass 2: PERSISTENT kernel (304 CTAs = 2/SM). Each CTA processes a balanced
// contiguous chunk of the 8192 (n, batch-tile) works with the half-tile
// cp.async pipeline. sB reloads only at n-boundaries (~2 per CTA).
// ---------------------------------------------------------------------------
#define LDA 136
#define SB_BYTES   (128 * LDA * 2)
#define SA_BYTES   (128 * LDA * 2)
#define STAGE_BYTES 32768
#define SMEM_TOTAL (SB_BYTES + SA_BYTES + STAGE_BYTES)   // 102400
#define NUM_CTAS   304
#define WORKS      (N_BLOCKS * (BATCH / 128))            // 8192

#define LDSM_X4(R0, R1, R2, R3, ADDR)                                          \
    asm volatile("ldmatrix.sync.aligned.m8n8.x4.shared.b16 {%0,%1,%2,%3}, [%4];" \
                 : "=r"(R0), "=r"(R1), "=r"(R2), "=r"(R3) : "r"(ADDR))

#define LDSM_X4_T(R0, R1, R2, R3, ADDR)                                        \
    asm volatile("ldmatrix.sync.aligned.m8n8.x4.trans.shared.b16 {%0,%1,%2,%3}, [%4];" \
                 : "=r"(R0), "=r"(R1), "=r"(R2), "=r"(R3) : "r"(ADDR))

#define MMA16816(D, A, B0, B1)                                                 \
    asm volatile("mma.sync.aligned.m16n8k16.row.col.f32.f16.f16.f32 "          \
                 "{%0,%1,%2,%3}, {%4,%5,%6,%7}, {%8,%9}, {%0,%1,%2,%3};"       \
                 : "+f"((D)[0]), "+f"((D)[1]), "+f"((D)[2]), "+f"((D)[3])      \
                 : "r"((A)[0]), "r"((A)[1]), "r"((A)[2]), "r"((A)[3]),         \
                   "r"(B0), "r"(B1))

__device__ __forceinline__ void cp16(uint32_t dst_smem, const void* src) {
    asm volatile("cp.async.cg.shared.global [%0], [%1], 16;" :: "r"(dst_smem), "l"(src));
}
#define CP_COMMIT() asm volatile("cp.async.commit_group;" ::: "memory")
#define CP_WAIT0()  asm volatile("cp.async.wait_group 0;" ::: "memory")

__device__ __forceinline__ void load_w(__half* sB, int n, int tid) {
    const uint4* wsrc = (const uint4*)(g_w + (size_t)n * (BLOCK_IN * BLOCK_OUT));
#pragma unroll
    for (int i = 0; i < 16; i++) {
        int idx = tid + i * 128;
        int r   = idx >> 4;
        int c   = (idx & 15) << 3;
        *(uint4*)&sB[r * LDA + c] = wsrc[idx];
    }
}

__device__ __forceinline__ void stage_half(const float* __restrict__ xb, int khalf,
                                           uint32_t stage_s, int tid) {
#pragma unroll
    for (int i = 0; i < 16; i++) {
        int idx = tid + i * 128;               // 0..2047
        int r   = idx >> 4;
        int k4  = (idx & 15) << 2;
        cp16(stage_s + idx * 16, xb + (size_t)r * LAYER_IN + khalf * 64 + k4);
    }
}

__device__ __forceinline__ void convert_half(const float* stage, __half* sA, int khalf, int tid) {
#pragma unroll
    for (int i = 0; i < 16; i++) {
        int idx = tid + i * 128;
        float4 v = *(const float4*)(stage + idx * 4);
        int r  = idx >> 4;
        int k4 = (idx & 15) << 2;
        __half2 h01 = __floats2half2_rn(v.x, v.y);
        __half2 h23 = __floats2half2_rn(v.z, v.w);
        uint2 pk = make_uint2(*(uint32_t*)&h01, *(uint32_t*)&h23);
        *(uint2*)&sA[r * LDA + khalf * 64 + k4] = pk;
    }
}

__global__ __launch_bounds__(128, 2)
void gemm_kernel(const float* __restrict__ x, float* __restrict__ out) {
    extern __shared__ char smem[];
    __half* sB   = (__half*)smem;
    __half* sA   = (__half*)(smem + SB_BYTES);
    float* stage = (float*)(smem + SB_BYTES + SA_BYTES);
    const uint32_t stage_s = smem_u32(stage);

    const int tid  = threadIdx.x;
    const int wid  = tid >> 5;
    const int lane = tid & 31;

    const int cta = blockIdx.x;
    const int w0 = (WORKS * cta) / NUM_CTAS;
    const int w1 = (WORKS * (cta + 1)) / NUM_CTAS;
    if (w0 >= w1) return;

    // ---- prologue: sB(n0) + sA(work w0) synchronously ----
    {
        int n0 = w0 >> 4, bt0 = w0 & 15;
        load_w(sB, n0, tid);
        const float* xb = x + (size_t)n0 * 128 + (size_t)(bt0 * 128) * LAYER_IN;
#pragma unroll
        for (int i = 0; i < 32; i++) {
            int idx = tid + i * 128;
            int r   = idx >> 5;
            int k4  = (idx & 31) << 2;
            float4 v = *(const float4*)(xb + (size_t)r * LAYER_IN + k4);
            __half2 h01 = __floats2half2_rn(v.x, v.y);
            __half2 h23 = __floats2half2_rn(v.z, v.w);
            uint2 pk = make_uint2(*(uint32_t*)&h01, *(uint32_t*)&h23);
            *(uint2*)&sA[r * LDA + k4] = pk;
        }
    }
    __syncthreads();

    const int warp_m = wid & 1;
    const int warp_n = wid >> 1;
    const int lr = lane & 15;
    const int lc = (lane >> 4) << 3;

    for (int w = w0; w < w1; w++) {
        const int n  = w >> 4;
        const int bt = w & 15;
        const bool pf = (w + 1 < w1);
        const int n2  = (w + 1) >> 4;
        const int bt2 = (w + 1) & 15;
        const float* xnext = x + (size_t)n2 * 128 + (size_t)(bt2 * 128) * LAYER_IN;

        if (pf) { stage_half(xnext, 0, stage_s, tid); CP_COMMIT(); }

        float acc[4][8][4];
#pragma unroll
        for (int mt = 0; mt < 4; mt++)
#pragma unroll
            for (int nt = 0; nt < 8; nt++)
#pragma unroll
                for (int j = 0; j < 4; j++) acc[mt][nt][j] = 0.f;

        // ---- ks 0..3: reads sA cols 0-63 ----
#pragma unroll
        for (int ks = 0; ks < 4; ks++) {
            const int k = ks * 16;
            uint32_t a[4][4];
#pragma unroll
            for (int mt = 0; mt < 4; mt++) {
                int row = warp_m * 64 + mt * 16 + lr;
                uint32_t addr = smem_u32(&sA[row * LDA + k + lc]);
                LDSM_X4(a[mt][0], a[mt][1], a[mt][2], a[mt][3], addr);
            }
            uint32_t b[8][2];
#pragma unroll
            for (int qq = 0; qq < 4; qq++) {
                int nn = warp_n * 64 + qq * 16;
                uint32_t addr = smem_u32(&sB[(k + lr) * LDA + nn + lc]);
                LDSM_X4_T(b[qq * 2][0], b[qq * 2][1], b[qq * 2 + 1][0], b[qq * 2 + 1][1], addr);
            }
#pragma unroll
            for (int mt = 0; mt < 4; mt++)
#pragma unroll
                for (int nt = 0; nt < 8; nt++)
                    MMA16816(acc[mt][nt], a[mt], b[nt][0], b[nt][1]);
        }

        // ---- mid: fold half0 into sA cols 0-63, launch half1 ----
        if (pf) {
            CP_WAIT0();
            __syncthreads();
            convert_half(stage, sA, 0, tid);
            stage_half(xnext, 1, stage_s, tid);
            CP_COMMIT();
        }

        // ---- ks 4..7: reads sA cols 64-127 ----
#pragma unroll
        for (int ks = 4; ks < 8; ks++) {
            const int k = ks * 16;
            uint32_t a[4][4];
#pragma unroll
            for (int mt = 0; mt < 4; mt++) {
                int row = warp_m * 64 + mt * 16 + lr;
                uint32_t addr = smem_u32(&sA[row * LDA + k + lc]);
                LDSM_X4(a[mt][0], a[mt][1], a[mt][2], a[mt][3], addr);
            }
            uint32_t b[8][2];
#pragma unroll
            for (int qq = 0; qq < 4; qq++) {
                int nn = warp_n * 64 + qq * 16;
                uint32_t addr = smem_u32(&sB[(k + lr) * LDA + nn + lc]);
                LDSM_X4_T(b[qq * 2][0], b[qq * 2][1], b[qq * 2 + 1][0], b[qq * 2 + 1][1], addr);
            }
#pragma unroll
            for (int mt = 0; mt < 4; mt++)
#pragma unroll
                for (int nt = 0; nt < 8; nt++)
                    MMA16816(acc[mt][nt], a[mt], b[nt][0], b[nt][1]);
        }

        // ---- epilogue (stores drain under the tail wait/convert) ----
        float* obase = out + (size_t)(bt * 128) * LAYER_OUT + (size_t)n * 128;
        const int er = lane >> 2;
        const int ec = (lane & 3) << 1;
#pragma unroll
        for (int mt = 0; mt < 4; mt++) {
#pragma unroll
            for (int nt = 0; nt < 8; nt++) {
                int r0 = warp_m * 64 + mt * 16 + er;
                int c0 = warp_n * 64 + nt * 8 + ec;
                *(float2*)(obase + (size_t)r0 * LAYER_OUT + c0) =
                    make_float2(acc[mt][nt][0], acc[mt][nt][1]);
                *(float2*)(obase + (size_t)(r0 + 8) * LAYER_OUT + c0) =
                    make_float2(acc[mt][nt][2], acc[mt][nt][3]);
            }
        }

        // ---- tail: fold half1; reload sB at n-boundary ----
        if (pf) {
            CP_WAIT0();
            __syncthreads();                 // all reads of sA & sB for work w done
            convert_half(stage, sA, 1, tid);
            if (n2 != n) load_w(sB, n2, tid);
            __syncthreads();
        }
    }
}

// ---------------------------------------------------------------------------
extern "C" void kernel_launch(void* const* d_in, const int* in_sizes, int n_in,
                              void* d_out, int out_size) {
    (void)in_sizes; (void)n_in; (void)out_size;
    const float* x = (const float*)d_in[0];
    const float* c = (const float*)d_in[1];
    float* out = (float*)d_out;

    cudaFuncSetAttribute(softmax_kernel, cudaFuncAttributeMaxDynamicSharedMemorySize, 73728);
    cudaFuncSetAttribute(gemm_kernel,    cudaFuncAttributeMaxDynamicSharedMemorySize, SMEM_TOTAL);

    softmax_kernel<<<N_BLOCKS, 512, 73728>>>(c);
    gemm_kernel<<<NUM_CTAS, 128, SMEM_TOTAL>>>(x, out);
}